// round 15
// baseline (speedup 1.0000x reference)
#include <cuda_runtime.h>
#include <cstdint>

// Problem constants
static constexpr int B = 2, N = 4, D = 48, H = 28, W = 60, C = 64;
static constexpr int DOWNSAMPLE = 8;
static constexpr int NX = 192, NY = 192, NZ = 1;
static constexpr float F_BEV = 4.0f;           // 1/SCALE
static constexpr float CX_BEV = 96.0f;         // NX/2 + OFFSETX
static constexpr float CY_BEV = 96.0f;         // NY/2
static constexpr float DMIN = 2.0f, DSTEP = 1.0f;

static constexpr int NCOL  = B * N * D * W;    // 23040 columns (b,n,d,w)
static constexpr int PLANE = NY * NX;          // 36864
static constexpr int STAGE_ELEMS = B * NZ * PLANE * C;  // 4,718,592 floats
static constexpr int STAGE_F4 = STAGE_ELEMS / 4;        // 1,179,648

// Channels-last accumulation buffer (18.9 MB, L2-resident)
__device__ __align__(16) float g_stage[STAGE_ELEMS];

// Coalesced vector atomic add (16 q-lanes -> 256B contiguous), no "memory"
// clobber (a clobber would serialize the preload stream).
#define RED_ADD_V4(ptr, vx, vy, vz, vw) \
    asm volatile("red.global.add.v4.f32 [%0], {%1, %2, %3, %4};" \
                 :: "l"(ptr), "f"(vx), "f"(vy), "f"(vz), "f"(vw))

// ---------------------------------------------------------------------------
// Kernel 0: zero the staging buffer. Grid-stride float4 loop.
// ---------------------------------------------------------------------------
__global__ void fp_zero_stage() {
    float4* s4 = reinterpret_cast<float4*>(g_stage);
    const float4 z = make_float4(0.f, 0.f, 0.f, 0.f);
    for (int i = blockIdx.x * blockDim.x + threadIdx.x; i < STAGE_F4;
         i += gridDim.x * blockDim.x) {
        s4[i] = z;
    }
}

// ---------------------------------------------------------------------------
// Per-(b,n) geometry precompute into shared memory: combine = R @ inv(K) + t.
// ---------------------------------------------------------------------------
__device__ __forceinline__ void fp_setup_geom(int i,
                                              const float* __restrict__ intr,
                                              const float* __restrict__ pose,
                                              float* __restrict__ s_geom) {
    const float* K = intr + i * 9;
    float a = K[0], b = K[1], c = K[2];
    float d = K[3], e = K[4], f = K[5];
    float g = K[6], h = K[7], ii = K[8];
    float A  = e * ii - f * h;
    float Bc = f * g - d * ii;
    float Cc = d * h - e * g;
    float inv_det = 1.0f / (a * A + b * Bc + c * Cc);
    float inv[9];
    inv[0] = A * inv_det;  inv[1] = (c * h - b * ii) * inv_det; inv[2] = (b * f - c * e) * inv_det;
    inv[3] = Bc * inv_det; inv[4] = (a * ii - c * g) * inv_det; inv[5] = (c * d - a * f) * inv_det;
    inv[6] = Cc * inv_det; inv[7] = (b * g - a * h) * inv_det;  inv[8] = (a * e - b * d) * inv_det;
    const float* P = pose + i * 16;
    for (int r = 0; r < 3; r++) {
        for (int cc = 0; cc < 3; cc++) {
            float s = 0.f;
            for (int k = 0; k < 3; k++) s += P[r * 4 + k] * inv[k * 3 + cc];
            s_geom[i * 12 + r * 3 + cc] = s;
        }
        s_geom[i * 12 + 9 + r] = P[r * 4 + 3];
    }
}

// ---------------------------------------------------------------------------
// Kernel 1: scatter into channels-last staging (b, vox, C).
// R13 structure (the fastest measured): warp = ONE column, lane = seg*16+q,
// depth-14 register preload (front-batched LDGs, MLP=14).
// NEW vs R13: flush is ONE red.global.add.v4.f32 into 256B-contiguous stage
// instead of 4 PLANE-strided scalar reds (41 cyc -> ~14 cyc LSU per flush
// warp-instr; frees the LSU for load issue).
// ---------------------------------------------------------------------------
__global__ __launch_bounds__(256) void fp_scatter(
        const float* __restrict__ x,
        const float* __restrict__ intr,
        const float* __restrict__ pose) {
    __shared__ float s_geom[B * N * 12];
    __shared__ int s_vox[8][28];                 // per-warp voxel table

    if (threadIdx.x < B * N) fp_setup_geom(threadIdx.x, intr, pose, s_geom);
    __syncthreads();

    const int gtid = blockIdx.x * 256 + threadIdx.x;   // 0 .. NCOL*32-1 (exact)
    const int lane = threadIdx.x & 31;
    const int wid  = threadIdx.x >> 5;                 // warp in block
    const int q    = lane & 15;
    const int seg  = lane >> 4;                        // 0: h<14, 1: h>=14
    const int cid  = gtid >> 5;                        // column (b,n,d,w)

    // decode column:  cid = ((b*N+n)*D + d)*W + w
    const int w   = cid % W;
    const int bnd = cid / W;              // (b*N+n)*D + d
    const int dd  = bnd % D;
    const int bn  = bnd / D;              // b*N + n
    const int b   = bn >> 2;              // /N

    const float* cm = s_geom + bn * 12;
    const float cm0 = cm[0], cm1 = cm[1], cm2 = cm[2], cm9  = cm[9];
    const float cm3 = cm[3], cm4 = cm[4], cm5 = cm[5], cm10 = cm[10];
    const float cm6 = cm[6], cm7 = cm[7], cm8 = cm[8], cm11 = cm[11];

    const float STEPX = (float)(W * DOWNSAMPLE - 1) / (float)(W - 1);
    const float STEPY = (float)(H * DOWNSAMPLE - 1) / (float)(H - 1);
    const float dep = DMIN + (float)dd * DSTEP;
    const float px  = ((float)w * STEPX) * dep;
    const float pz  = dep;

    // --- Phase 1: lane evaluates geometry for h = lane (lane < 28) ---
    // identical fmaf chains to the verified kernels (bin-boundary stability)
    int veval = -1;
    if (lane < H) {
        float v  = (float)lane * STEPY;
        float py = v * dep;
        float gxf = fmaf(cm0, px, fmaf(cm1, py, fmaf(cm2, pz, cm9)));
        float gyf = fmaf(cm3, px, fmaf(cm4, py, fmaf(cm5, pz, cm10)));
        float gzf = fmaf(cm6, px, fmaf(cm7, py, fmaf(cm8, pz, cm11)));
        int gx = (int)(gxf * F_BEV + CX_BEV);     // trunc == astype(int32)
        int gy = (int)(gyf * F_BEV + CY_BEV);
        int gz = (int)((gzf + 10.0f) / 20.0f);
        bool kept = (gx >= 0) & (gx < NX) & (gy >= 0) & (gy < NY) & (gz >= 0) & (gz < NZ);
        if (kept) veval = (gz * NY + gy) * NX + gx;   // NZ=1 -> plane index
    }
    if (lane < H) s_vox[wid][lane] = veval;
    unsigned mask = __ballot_sync(0xffffffffu, veval >= 0);  // bits 0..27
    __syncwarp();
    if (mask == 0u) return;                   // whole column dead (warp exit)

    // --- this lane's segment kept span ---
    const int base = seg * 14;
    unsigned m = (mask >> base) & 0x3FFFu;    // 14 bits
    if (m == 0u) return;                      // this half-column keeps nothing
    const int hmin = base + (__ffs(m) - 1);
    const int span = (31 - __clz(m)) - (__ffs(m) - 1);   // 0..13

    // --- Phase 2a: PRELOAD all 14 float4 (clamped addresses) into registers.
    const float* xp0 = x + ((size_t)(bnd * H + hmin) * W + w) * C + q * 4;
    const size_t hstride = (size_t)W * C;

    float4 vals[14];
    #pragma unroll
    for (int j = 0; j < 14; j++) {
        const int jc = (j <= span) ? j : span;   // clamp -> always-valid address
        vals[j] = *reinterpret_cast<const float4*>(xp0 + (size_t)jc * hstride);
    }

    // --- Phase 2b: run-length accumulate + coalesced v4 flush into stage ---
    float* const stagebase = g_stage + ((size_t)b * PLANE) * C + q * 4;
    const int* const vt = s_vox[wid];

    int curv = -1;
    float4 acc = make_float4(0.f, 0.f, 0.f, 0.f);

    #pragma unroll
    for (int j = 0; j < 14; j++) {
        const int h = hmin + j;
        const bool live = (j <= span) && ((mask >> h) & 1u);
        if (live) {
            const int vox = vt[h];               // LDS broadcast across q-lanes
            const float4 val = vals[j];
            if (vox == curv) {
                acc.x += val.x; acc.y += val.y; acc.z += val.z; acc.w += val.w;
            } else {
                if (curv >= 0) {
                    float* dst = stagebase + (size_t)curv * C;
                    RED_ADD_V4(dst, acc.x, acc.y, acc.z, acc.w);
                }
                curv = vox;
                acc = val;
            }
        }
    }
    if (curv >= 0) {
        float* dst = stagebase + (size_t)curv * C;
        RED_ADD_V4(dst, acc.x, acc.y, acc.z, acc.w);
    }
}

// ---------------------------------------------------------------------------
// Kernel 2: transpose stage (B, NZ, NY, NX, C) -> out (B, NZ*C, NY, NX).
// 64x64 tile (c covers full C=64), float4 on both global sides.
// (verified correct in R3)
// ---------------------------------------------------------------------------
__global__ void fp_transpose(float* __restrict__ out) {
    __shared__ float tile[64][65];   // tile[c][x]
    int xt = blockIdx.x;             // 0..NX/64-1
    int y  = blockIdx.y;
    int bz = blockIdx.z;             // b*NZ + z
    int t  = threadIdx.x;            // 256 threads

    const float4* src = reinterpret_cast<const float4*>(
        g_stage + ((size_t)(bz * NY + y) * NX + xt * 64) * C);
    #pragma unroll
    for (int p = 0; p < 4; p++) {
        int e  = p * 256 + t;
        int xr = e >> 4;             // x within tile
        int cq = e & 15;             // c quad
        float4 v = src[xr * 16 + cq];
        tile[cq * 4 + 0][xr] = v.x;
        tile[cq * 4 + 1][xr] = v.y;
        tile[cq * 4 + 2][xr] = v.z;
        tile[cq * 4 + 3][xr] = v.w;
    }
    __syncthreads();
    int b = bz / NZ, z = bz % NZ;
    #pragma unroll
    for (int p = 0; p < 4; p++) {
        int e  = p * 256 + t;
        int cr = e >> 4;             // channel row
        int xq = e & 15;             // x quad
        float4 v = make_float4(tile[cr][xq * 4 + 0], tile[cr][xq * 4 + 1],
                               tile[cr][xq * 4 + 2], tile[cr][xq * 4 + 3]);
        float4* dstv = reinterpret_cast<float4*>(
            out + ((size_t)((b * NZ + z) * C + cr) * NY + y) * NX + xt * 64);
        dstv[xq] = v;
    }
}

// ---------------------------------------------------------------------------
extern "C" void kernel_launch(void* const* d_in, const int* in_sizes, int n_in,
                              void* d_out, int out_size) {
    const float* x    = (const float*)d_in[0];
    const float* intr = (const float*)d_in[1];
    const float* pose = (const float*)d_in[2];
    float* out = (float*)d_out;

    // zero staging (out itself is fully overwritten by the transpose)
    fp_zero_stage<<<1184, 256>>>();

    // NCOL*32 = 737,280 threads = 2880 blocks x 256 (exact)
    fp_scatter<<<2880, 256>>>(x, intr, pose);

    // (NX/64, NY, B*NZ) = (3, 192, 2)
    {
        dim3 grid(NX / 64, NY, B * NZ);
        fp_transpose<<<grid, 256>>>(out);
    }
}